// round 16
// baseline (speedup 1.0000x reference)
#include <cuda_runtime.h>
#include <cuda_fp16.h>

typedef unsigned int u32;

// ---- problem constants ----
constexpr int S = 4096, D = 64, BH = 32;
constexpr int WIN = 512, GQ = 64, QB = 256, CK = 64;
constexpr int NCH = (WIN + QB) / CK;           // 12
constexpr float SCALE = 0.125f;
constexpr int SPLITS = 16, KPS = S / SPLITS;   // 256 keys per split
constexpr int NT = 512;                        // banded CTA threads

// scratch for split-K global prefix (plain sums; |s| small)
__device__ float g_pl[BH][SPLITS][GQ];
__device__ float g_pacc[BH][SPLITS][GQ][D];

// ---- fp16 plane geometry (padded rows: 72 halves = 144 B) ----
constexpr int RSB = 144;
// banded planes: Q (256 rows) + double-buffered K/V
constexpr int OFF_QH = 0;                      // Q [256 x 64]
constexpr int OFF_K0 = OFF_QH + 256 * RSB;     // 36864
constexpr int OFF_V0 = OFF_K0 + 64 * RSB;
constexpr int OFF_K1 = OFF_V0 + 64 * RSB;
constexpr int OFF_V1 = OFF_K1 + 64 * RSB;
constexpr int BANDED_BYTES = OFF_V1 + 64 * RSB;   // 73728
// global path: per-quarter plane block (Q 64, K 64, V 64)
constexpr int GHB = 3 * 64 * RSB;              // 27648 per quarter
constexpr int GOFF_Q = 0;
constexpr int GOFF_K = GOFF_Q + 64 * RSB;
constexpr int GOFF_V = GOFF_K + 64 * RSB;
constexpr int SMEM_BYTES = 4 * GHB;            // 110592 (covers both paths)

// ---- helpers ----
__device__ __forceinline__ u32 smem_u32(const void* p) {
    u32 a;
    asm("{ .reg .u64 t; cvta.to.shared.u64 t, %1; cvt.u32.u64 %0, t; }" : "=r"(a) : "l"(p));
    return a;
}
__device__ __forceinline__ u32 h2(float a, float b) {   // pack {lo=a, hi=b} fp16x2
    u32 r;
    asm("cvt.rn.f16x2.f32 %0, %1, %2;" : "=r"(r) : "f"(b), "f"(a));
    return r;
}
__device__ __forceinline__ void ldsm_x4(u32* r, u32 a) {
    asm volatile("ldmatrix.sync.aligned.m8n8.x4.shared.b16 {%0,%1,%2,%3}, [%4];"
                 : "=r"(r[0]), "=r"(r[1]), "=r"(r[2]), "=r"(r[3]) : "r"(a));
}
__device__ __forceinline__ void ldsm_x4t(u32* r, u32 a) {
    asm volatile("ldmatrix.sync.aligned.m8n8.x4.trans.shared.b16 {%0,%1,%2,%3}, [%4];"
                 : "=r"(r[0]), "=r"(r[1]), "=r"(r[2]), "=r"(r[3]) : "r"(a));
}
__device__ __forceinline__ void mma_f16(float* d, const u32* a, const u32* b) {
    asm volatile("mma.sync.aligned.m16n8k16.row.col.f32.f16.f16.f32 "
                 "{%0,%1,%2,%3}, {%4,%5,%6,%7}, {%8,%9}, {%0,%1,%2,%3};"
                 : "+f"(d[0]), "+f"(d[1]), "+f"(d[2]), "+f"(d[3])
                 : "r"(a[0]), "r"(a[1]), "r"(a[2]), "r"(a[3]), "r"(b[0]), "r"(b[1]));
}

// =====================================================================
// banded path: 16 warps x 16 q-rows (QB=256), pure fp16 HMMA,
// software-pipelined double-buffered K/V (8-reg prefetch, split-phase).
// =====================================================================
__device__ __forceinline__ void banded_body(
    char* sm, u32 sb, const float* __restrict__ q, const float* __restrict__ k,
    const float* __restrict__ v, float* __restrict__ out, int bh, int qs) {
    const int tid = threadIdx.x, w = tid >> 5, lane = tid & 31;
    const size_t base = (size_t)bh * S * D;

    // Q load (2 threads/row), fold SCALE, convert fp16
    {
        const int row = tid >> 1, hf = tid & 1;
        const float4* qp = (const float4*)(q + base + (size_t)(qs + row) * D + hf * 32);
#pragma unroll
        for (int t = 0; t < 8; ++t) {
            float4 x = qp[t];
            *(uint2*)(sm + OFF_QH + (u32)(row * RSB + hf * 64 + t * 8)) =
                make_uint2(h2(x.x * SCALE, x.y * SCALE), h2(x.z * SCALE, x.w * SCALE));
        }
    }

    const int ch0 = (qs >= WIN) ? 0 : (WIN - qs) / CK;
    // preload chunk ch0 directly into buffer 0
    {
        const int j0 = qs - WIN + ch0 * CK;
#pragma unroll
        for (int t = 0; t < 2; ++t) {
            int idx = tid + t * NT, row = idx >> 4, c4 = idx & 15;
            u32 o = (u32)(row * RSB + c4 * 8);
            float4 x = *(const float4*)(k + base + (size_t)(j0 + row) * D + c4 * 4);
            *(uint2*)(sm + OFF_K0 + o) = make_uint2(h2(x.x, x.y), h2(x.z, x.w));
            float4 y = *(const float4*)(v + base + (size_t)(j0 + row) * D + c4 * 4);
            *(uint2*)(sm + OFF_V0 + o) = make_uint2(h2(y.x, y.y), h2(y.z, y.w));
        }
    }
    __syncthreads();

    // hoist Q fragments
    const u32 qrow_a = (u32)((w * 16 + (lane & 15)) * RSB + (lane >> 4) * 16);
    u32 aq[16];
#pragma unroll
    for (int ks = 0; ks < 4; ++ks)
        ldsm_x4(aq + 4 * ks, sb + OFF_QH + qrow_a + (u32)(ks * 32));

    float O[8][4];
#pragma unroll
    for (int nt = 0; nt < 8; ++nt)
#pragma unroll
        for (int c = 0; c < 4; ++c) O[nt][c] = 0.f;
    float lsum[2] = {0.f, 0.f};

    const int ilo = qs + w * 16, ihi = ilo + 15;
    const u32 kq_b = (u32)(((lane >> 4) * 8 + (lane & 7)) * RSB + ((lane >> 3) & 1) * 16);
    const u32 vq_b = (u32)((lane & 15) * RSB + (lane >> 4) * 16);

#pragma unroll 1
    for (int ch = ch0; ch < NCH; ++ch) {
        const int j0 = qs - WIN + ch * CK;
        const int b = (ch - ch0) & 1;
        const u32 kb_s = sb + (b ? OFF_K1 : OFF_K0);
        const u32 vb_s = sb + (b ? OFF_V1 : OFF_V0);
        const bool more = (ch + 1 < NCH);

        // ---- prefetch K(ch+1) into registers (latency overlapped by QK) ----
        float4 kreg[2];
        if (more) {
            const int j1 = j0 + CK;
#pragma unroll
            for (int t = 0; t < 2; ++t) {
                int idx = tid + t * NT, row = idx >> 4, c4 = idx & 15;
                kreg[t] = *(const float4*)(k + base + (size_t)(j1 + row) * D + c4 * 4);
            }
        }

        bool act[4];
#pragma unroll
        for (int g = 0; g < 4; ++g) {
            int jlo = j0 + g * 16, jhi = jlo + 15;
            act[g] = (jlo <= ihi) && (ilo - jhi < WIN);
        }

        // ---- QK on buffer b ----
        float Sc[8][4];
#pragma unroll
        for (int nt = 0; nt < 8; ++nt)
#pragma unroll
            for (int c = 0; c < 4; ++c) Sc[nt][c] = 0.f;

#pragma unroll
        for (int ntp = 0; ntp < 4; ++ntp) {
            if (!act[ntp]) continue;
#pragma unroll
            for (int ks = 0; ks < 4; ++ks) {
                u32 b4[4];
                ldsm_x4(b4, kb_s + kq_b + (u32)(ntp * 16 * RSB + ks * 32));
                mma_f16(Sc[2 * ntp], aq + 4 * ks, b4);
                mma_f16(Sc[2 * ntp + 1], aq + 4 * ks, b4 + 2);
            }
        }

        // ---- mask + exp + row-sum + pack P ----
        u32 PH[4][4];
        const int ibase = ilo + (lane >> 2);
#pragma unroll
        for (int g = 0; g < 4; ++g) {
            if (!act[g]) continue;
#pragma unroll
            for (int h = 0; h < 2; ++h) {
                const int nt = 2 * g + h;
                const int jb = j0 + nt * 8 + (lane & 3) * 2;
#pragma unroll
                for (int c = 0; c < 4; ++c) {
                    int i = ibase + ((c >= 2) ? 8 : 0);
                    int j = jb + (c & 1);
                    float p = ((u32)(i - j) < (u32)WIN) ? __expf(Sc[nt][c]) : 0.f;
                    Sc[nt][c] = p;
                    lsum[c >> 1] += p;
                }
            }
            PH[g][0] = h2(Sc[2 * g][0],     Sc[2 * g][1]);
            PH[g][1] = h2(Sc[2 * g][2],     Sc[2 * g][3]);
            PH[g][2] = h2(Sc[2 * g + 1][0], Sc[2 * g + 1][1]);
            PH[g][3] = h2(Sc[2 * g + 1][2], Sc[2 * g + 1][3]);
        }

        // ---- store K(ch+1) to other buffer; reuse regs to prefetch V(ch+1) ----
        if (more) {
            const int j1 = j0 + CK;
            char* kd = sm + (b ? OFF_K0 : OFF_K1);
#pragma unroll
            for (int t = 0; t < 2; ++t) {
                int idx = tid + t * NT, row = idx >> 4, c4 = idx & 15;
                *(uint2*)(kd + row * RSB + c4 * 8) =
                    make_uint2(h2(kreg[t].x, kreg[t].y), h2(kreg[t].z, kreg[t].w));
                kreg[t] = *(const float4*)(v + base + (size_t)(j1 + row) * D + c4 * 4);
            }
        }

        // ---- PV on buffer b (covers V prefetch latency) ----
#pragma unroll
        for (int k2 = 0; k2 < 4; ++k2) {
            if (!act[k2]) continue;
#pragma unroll
            for (int dg = 0; dg < 4; ++dg) {
                u32 v4[4];
                ldsm_x4t(v4, vb_s + vq_b + (u32)(k2 * 16 * RSB + dg * 32));
                mma_f16(O[2 * dg], PH[k2], v4);
                mma_f16(O[2 * dg + 1], PH[k2], v4 + 2);
            }
        }

        // ---- store V(ch+1) to other buffer ----
        if (more) {
            char* vd = sm + (b ? OFF_V0 : OFF_V1);
#pragma unroll
            for (int t = 0; t < 2; ++t) {
                int idx = tid + t * NT, row = idx >> 4, c4 = idx & 15;
                *(uint2*)(vd + row * RSB + c4 * 8) =
                    make_uint2(h2(kreg[t].x, kreg[t].y), h2(kreg[t].z, kreg[t].w));
            }
        }
        __syncthreads();
    }

    // ---- finalize ----
#pragma unroll
    for (int i = 0; i < 2; ++i) {
        lsum[i] += __shfl_xor_sync(0xffffffffu, lsum[i], 1);
        lsum[i] += __shfl_xor_sync(0xffffffffu, lsum[i], 2);
    }
#pragma unroll
    for (int up = 0; up < 2; ++up) {
        float inv = 1.f / lsum[up];
        int i = ilo + (lane >> 2) + up * 8;
#pragma unroll
        for (int nt = 0; nt < 8; ++nt) {
            int dcol = nt * 8 + (lane & 3) * 2;
            *(float2*)(out + base + (size_t)i * D + dcol) =
                make_float2(O[nt][2 * up] * inv, O[nt][2 * up + 1] * inv);
        }
    }
}

// =====================================================================
// global-prefix path: one 128-thread quarter handles one split (4 chunks).
// htid in [0,128); smem plane at sm + quarter*GHB.
// =====================================================================
__device__ __forceinline__ void global_body(
    char* sm, u32 sb, const float* __restrict__ q, const float* __restrict__ k,
    const float* __restrict__ v, int bh, int sp, int htid) {
    const int w = htid >> 5, lane = htid & 31;
    const size_t base = (size_t)bh * S * D;
    const int k0 = sp * KPS;

    {
        const int row = htid >> 1, hf = htid & 1;
        const float4* qp = (const float4*)(q + base + (size_t)row * D + hf * 32);
#pragma unroll
        for (int t = 0; t < 8; ++t) {
            float4 x = qp[t];
            *(uint2*)(sm + GOFF_Q + (u32)(row * RSB + hf * 64 + t * 8)) =
                make_uint2(h2(x.x * SCALE, x.y * SCALE), h2(x.z * SCALE, x.w * SCALE));
        }
    }
    __syncthreads();

    const u32 qrow_a = (u32)((w * 16 + (lane & 15)) * RSB + (lane >> 4) * 16);
    u32 aq[16];
#pragma unroll
    for (int ks = 0; ks < 4; ++ks)
        ldsm_x4(aq + 4 * ks, sb + GOFF_Q + qrow_a + (u32)(ks * 32));

    float O[8][4];
#pragma unroll
    for (int nt = 0; nt < 8; ++nt)
#pragma unroll
        for (int c = 0; c < 4; ++c) O[nt][c] = 0.f;
    float lsum[2] = {0.f, 0.f};

    const u32 kq_b = (u32)(((lane >> 4) * 8 + (lane & 7)) * RSB + ((lane >> 3) & 1) * 16);
    const u32 vq_b = (u32)((lane & 15) * RSB + (lane >> 4) * 16);

#pragma unroll 1
    for (int ch = 0; ch < KPS / CK; ++ch) {
        const int j0 = k0 + ch * CK;

        __syncthreads();
        {
            const int r = htid >> 1, hf = htid & 1;
            const float4* kp = (const float4*)(k + base + (size_t)(j0 + r) * D + hf * 32);
            const float4* vp = (const float4*)(v + base + (size_t)(j0 + r) * D + hf * 32);
#pragma unroll
            for (int t = 0; t < 8; ++t) {
                u32 o = (u32)(r * RSB + hf * 64 + t * 8);
                float4 x = kp[t];
                *(uint2*)(sm + GOFF_K + o) = make_uint2(h2(x.x, x.y), h2(x.z, x.w));
                float4 y = vp[t];
                *(uint2*)(sm + GOFF_V + o) = make_uint2(h2(y.x, y.y), h2(y.z, y.w));
            }
        }
        __syncthreads();

        float Sc[8][4];
#pragma unroll
        for (int nt = 0; nt < 8; ++nt)
#pragma unroll
            for (int c = 0; c < 4; ++c) Sc[nt][c] = 0.f;

#pragma unroll
        for (int ntp = 0; ntp < 4; ++ntp) {
#pragma unroll
            for (int ks = 0; ks < 4; ++ks) {
                u32 b4[4];
                ldsm_x4(b4, sb + GOFF_K + kq_b + (u32)(ntp * 16 * RSB + ks * 32));
                mma_f16(Sc[2 * ntp], aq + 4 * ks, b4);
                mma_f16(Sc[2 * ntp + 1], aq + 4 * ks, b4 + 2);
            }
        }

        u32 PH[4][4];
#pragma unroll
        for (int nt = 0; nt < 8; ++nt)
#pragma unroll
            for (int c = 0; c < 4; ++c) {
                float p = __expf(Sc[nt][c]);
                Sc[nt][c] = p;
                lsum[c >> 1] += p;
            }
#pragma unroll
        for (int k2 = 0; k2 < 4; ++k2) {
            PH[k2][0] = h2(Sc[2 * k2][0],     Sc[2 * k2][1]);
            PH[k2][1] = h2(Sc[2 * k2][2],     Sc[2 * k2][3]);
            PH[k2][2] = h2(Sc[2 * k2 + 1][0], Sc[2 * k2 + 1][1]);
            PH[k2][3] = h2(Sc[2 * k2 + 1][2], Sc[2 * k2 + 1][3]);
        }

#pragma unroll
        for (int k2 = 0; k2 < 4; ++k2) {
#pragma unroll
            for (int dg = 0; dg < 4; ++dg) {
                u32 v4[4];
                ldsm_x4t(v4, sb + GOFF_V + vq_b + (u32)(k2 * 16 * RSB + dg * 32));
                mma_f16(O[2 * dg], PH[k2], v4);
                mma_f16(O[2 * dg + 1], PH[k2], v4 + 2);
            }
        }
    }

#pragma unroll
    for (int i = 0; i < 2; ++i) {
        lsum[i] += __shfl_xor_sync(0xffffffffu, lsum[i], 1);
        lsum[i] += __shfl_xor_sync(0xffffffffu, lsum[i], 2);
    }
#pragma unroll
    for (int up = 0; up < 2; ++up) {
        int i = w * 16 + (lane >> 2) + up * 8;
        if ((lane & 3) == 0) g_pl[bh][sp][i] = lsum[up];
#pragma unroll
        for (int nt = 0; nt < 8; ++nt) {
            int dcol = nt * 8 + (lane & 3) * 2;
            *(float2*)&g_pacc[bh][sp][i][dcol] =
                make_float2(O[nt][2 * up], O[nt][2 * up + 1]);
        }
    }
}

// =====================================================================
// Merged kernel: x<16 -> banded 256-row tile; x>=16 -> 4 global quarters.
// =====================================================================
__global__ void __launch_bounds__(NT, 1)
swa_fused(const float* __restrict__ q, const float* __restrict__ k,
          const float* __restrict__ v, float* __restrict__ out) {
    extern __shared__ __align__(128) char sm[];
    const u32 sb0 = smem_u32(sm);
    const int bh = blockIdx.y;

    if (blockIdx.x < (S / QB)) {
        banded_body(sm, sb0, q, k, v, out, bh, blockIdx.x * QB);
    } else {
        const int qtr = threadIdx.x >> 7;           // 0..3
        const int htid = threadIdx.x & 127;
        const int sp = (blockIdx.x - (S / QB)) * 4 + qtr;
        global_body(sm + qtr * GHB, sb0 + qtr * GHB, q, k, v, bh, sp, htid);
    }
}

// =====================================================================
// combine split-K partials (plain sums), overwrite rows [0, GQ)
// =====================================================================
__global__ void __launch_bounds__(D, 1)
swa_combine(float* __restrict__ out) {
    const int bh = blockIdx.y;
    const int qi = blockIdx.x;
    const int d = threadIdx.x;

    float den = 0.f, num = 0.f;
#pragma unroll
    for (int s = 0; s < SPLITS; ++s) {
        den += g_pl[bh][s][qi];
        num += g_pacc[bh][s][qi][d];
    }
    out[(size_t)bh * S * D + (size_t)qi * D + d] = num / den;
}

// =====================================================================
extern "C" void kernel_launch(void* const* d_in, const int* in_sizes, int n_in,
                              void* d_out, int out_size) {
    const float* q = (const float*)d_in[0];
    const float* k = (const float*)d_in[1];
    const float* v = (const float*)d_in[2];
    float* out = (float*)d_out;
    (void)in_sizes; (void)n_in; (void)out_size;

    cudaFuncSetAttribute(swa_fused,
                         cudaFuncAttributeMaxDynamicSharedMemorySize, SMEM_BYTES);

    dim3 g1(S / QB + SPLITS / 4, BH);   // 16 banded tiles + 4 global quads
    swa_fused<<<g1, NT, SMEM_BYTES>>>(q, k, v, out);

    dim3 g3(GQ, BH);
    swa_combine<<<g3, D>>>(out);
}

// round 17
// speedup vs baseline: 1.0781x; 1.0781x over previous
#include <cuda_runtime.h>
#include <cuda_fp16.h>

typedef unsigned int u32;

// ---- problem constants ----
constexpr int S = 4096, D = 64, BH = 32;
constexpr int WIN = 512, GQ = 64, QB = 128, CK = 64, NCH = 10;
constexpr float SCALE = 0.125f;
constexpr float LOG2E = 1.44269504088896f;
constexpr int SPLITS = 16, KPS = S / SPLITS;   // 256 keys per split

// scratch for split-K global prefix (plain sums; |s| small)
__device__ float g_pl[BH][SPLITS][GQ];
__device__ float g_pacc[BH][SPLITS][GQ][D];

// ---- fp16 plane geometry (padded rows: 72 halves = 144 B) ----
constexpr int RSB = 144;
// banded planes: Q + double-buffered K/V
constexpr int OFF_QH = 0;                    // Q [128 x 64]
constexpr int OFF_K0 = OFF_QH + 128 * RSB;   // K buf0 [64 x 64]
constexpr int OFF_V0 = OFF_K0 + 64 * RSB;
constexpr int OFF_K1 = OFF_V0 + 64 * RSB;
constexpr int OFF_V1 = OFF_K1 + 64 * RSB;
constexpr int SMEM_BYTES = OFF_V1 + 64 * RSB;   // 55296
// global path: per-half plane block (Q 64 rows, K 64, V 64)
constexpr int GHB = 3 * 64 * RSB;            // 27648 per half (2*GHB == SMEM_BYTES)
constexpr int GOFF_Q = 0;
constexpr int GOFF_K = GOFF_Q + 64 * RSB;
constexpr int GOFF_V = GOFF_K + 64 * RSB;

// ---- helpers ----
__device__ __forceinline__ u32 smem_u32(const void* p) {
    u32 a;
    asm("{ .reg .u64 t; cvta.to.shared.u64 t, %1; cvt.u32.u64 %0, t; }" : "=r"(a) : "l"(p));
    return a;
}
__device__ __forceinline__ u32 h2(float a, float b) {   // pack {lo=a, hi=b} fp16x2
    u32 r;
    asm("cvt.rn.f16x2.f32 %0, %1, %2;" : "=r"(r) : "f"(b), "f"(a));
    return r;
}
__device__ __forceinline__ float ex2f(float x) {        // exp2 via MUFU, no FMUL
    float r;
    asm("ex2.approx.f32 %0, %1;" : "=f"(r) : "f"(x));
    return r;
}
__device__ __forceinline__ void ldsm_x4(u32* r, u32 a) {
    asm volatile("ldmatrix.sync.aligned.m8n8.x4.shared.b16 {%0,%1,%2,%3}, [%4];"
                 : "=r"(r[0]), "=r"(r[1]), "=r"(r[2]), "=r"(r[3]) : "r"(a));
}
__device__ __forceinline__ void ldsm_x4t(u32* r, u32 a) {
    asm volatile("ldmatrix.sync.aligned.m8n8.x4.trans.shared.b16 {%0,%1,%2,%3}, [%4];"
                 : "=r"(r[0]), "=r"(r[1]), "=r"(r[2]), "=r"(r[3]) : "r"(a));
}
__device__ __forceinline__ void mma_f16(float* d, const u32* a, const u32* b) {
    asm volatile("mma.sync.aligned.m16n8k16.row.col.f32.f16.f16.f32 "
                 "{%0,%1,%2,%3}, {%4,%5,%6,%7}, {%8,%9}, {%0,%1,%2,%3};"
                 : "+f"(d[0]), "+f"(d[1]), "+f"(d[2]), "+f"(d[3])
                 : "r"(a[0]), "r"(a[1]), "r"(a[2]), "r"(a[3]), "r"(b[0]), "r"(b[1]));
}

// =====================================================================
// banded path: 8 warps x 16 q-rows, pure fp16 HMMA,
// double-buffered K/V pipeline; exp2-domain softmax; ones-MMA row sums.
// =====================================================================
__device__ __forceinline__ void banded_body(
    char* sm, u32 sb, const float* __restrict__ q, const float* __restrict__ k,
    const float* __restrict__ v, float* __restrict__ out, int bh, int qs) {
    const int tid = threadIdx.x, w = tid >> 5, lane = tid & 31;
    const size_t base = (size_t)bh * S * D;
    const float NINF = __int_as_float(0xff800000);
    const u32 ones2[2] = {0x3C003C00u, 0x3C003C00u};   // fp16 1.0 x4

    // Q load (2 threads/row), fold SCALE*log2e, convert fp16
    {
        const int row = tid >> 1, hf = tid & 1;
        const float4* qp = (const float4*)(q + base + (size_t)(qs + row) * D + hf * 32);
        const float sc = SCALE * LOG2E;
#pragma unroll
        for (int t = 0; t < 8; ++t) {
            float4 x = qp[t];
            *(uint2*)(sm + OFF_QH + (u32)(row * RSB + hf * 64 + t * 8)) =
                make_uint2(h2(x.x * sc, x.y * sc), h2(x.z * sc, x.w * sc));
        }
    }

    const int ch0 = (qs >= WIN) ? 0 : (WIN - qs) / CK;
    // preload chunk ch0 directly into buffer 0
    {
        const int j0 = qs - WIN + ch0 * CK;
        const int r = tid >> 2, qt = tid & 3;
        const float4* kp = (const float4*)(k + base + (size_t)(j0 + r) * D + qt * 16);
        const float4* vp = (const float4*)(v + base + (size_t)(j0 + r) * D + qt * 16);
#pragma unroll
        for (int t = 0; t < 4; ++t) {
            u32 o = (u32)(r * RSB + qt * 32 + t * 8);
            float4 x = kp[t];
            *(uint2*)(sm + OFF_K0 + o) = make_uint2(h2(x.x, x.y), h2(x.z, x.w));
            float4 y = vp[t];
            *(uint2*)(sm + OFF_V0 + o) = make_uint2(h2(y.x, y.y), h2(y.z, y.w));
        }
    }
    __syncthreads();

    // hoist Q fragments
    const u32 qrow_a = (u32)((w * 16 + (lane & 15)) * RSB + (lane >> 4) * 16);
    u32 aq[16];
#pragma unroll
    for (int ks = 0; ks < 4; ++ks)
        ldsm_x4(aq + 4 * ks, sb + OFF_QH + qrow_a + (u32)(ks * 32));

    float O[8][4];
#pragma unroll
    for (int nt = 0; nt < 8; ++nt)
#pragma unroll
        for (int c = 0; c < 4; ++c) O[nt][c] = 0.f;
    float Lone[4] = {0.f, 0.f, 0.f, 0.f};   // ones-MMA row-sum accumulator

    const int ilo = qs + w * 16, ihi = ilo + 15;
    const u32 kq_b = (u32)(((lane >> 4) * 8 + (lane & 7)) * RSB + ((lane >> 3) & 1) * 16);
    const u32 vq_b = (u32)((lane & 15) * RSB + (lane >> 4) * 16);

#pragma unroll 1
    for (int ch = ch0; ch < NCH; ++ch) {
        const int j0 = qs - WIN + ch * CK;
        const int b = (ch - ch0) & 1;
        const u32 kb_s = sb + (b ? OFF_K1 : OFF_K0);
        const u32 vb_s = sb + (b ? OFF_V1 : OFF_V0);
        const bool more = (ch + 1 < NCH);

        // ---- prefetch K(ch+1) into registers (latency overlapped by QK) ----
        float4 kreg[4];
        if (more) {
            const int j1 = j0 + CK;
#pragma unroll
            for (int t = 0; t < 4; ++t) {
                int idx = tid + t * 256, row = idx >> 4, c4 = idx & 15;
                kreg[t] = *(const float4*)(k + base + (size_t)(j1 + row) * D + c4 * 4);
            }
        }

        bool act[4];
#pragma unroll
        for (int g = 0; g < 4; ++g) {
            int jlo = j0 + g * 16, jhi = jlo + 15;
            act[g] = (jlo <= ihi) && (ilo - jhi < WIN);
        }

        // ---- QK on buffer b ----
        float Sc[8][4];
#pragma unroll
        for (int nt = 0; nt < 8; ++nt)
#pragma unroll
            for (int c = 0; c < 4; ++c) Sc[nt][c] = 0.f;

#pragma unroll
        for (int ntp = 0; ntp < 4; ++ntp) {
            if (!act[ntp]) continue;
#pragma unroll
            for (int ks = 0; ks < 4; ++ks) {
                u32 b4[4];
                ldsm_x4(b4, kb_s + kq_b + (u32)(ntp * 16 * RSB + ks * 32));
                mma_f16(Sc[2 * ntp], aq + 4 * ks, b4);
                mma_f16(Sc[2 * ntp + 1], aq + 4 * ks, b4 + 2);
            }
        }

        // ---- mask (boundary groups only) + exp2 + pack P ----
        u32 PH[4][4];
        const int ibase = ilo + (lane >> 2);
#pragma unroll
        for (int g = 0; g < 4; ++g) {
            if (!act[g]) continue;
            const int jlo = j0 + g * 16, jhi = jlo + 15;
            const bool fullv = (jhi <= ilo) && (ihi - jlo < WIN);
            if (!fullv) {
#pragma unroll
                for (int h = 0; h < 2; ++h) {
                    const int nt = 2 * g + h;
                    const int jb = j0 + nt * 8 + (lane & 3) * 2;
#pragma unroll
                    for (int c = 0; c < 4; ++c) {
                        int i = ibase + ((c >= 2) ? 8 : 0);
                        int j = jb + (c & 1);
                        if ((u32)(i - j) >= (u32)WIN) Sc[nt][c] = NINF;
                    }
                }
            }
#pragma unroll
            for (int h = 0; h < 2; ++h) {
                const int nt = 2 * g + h;
#pragma unroll
                for (int c = 0; c < 4; ++c) Sc[nt][c] = ex2f(Sc[nt][c]);
            }
            PH[g][0] = h2(Sc[2 * g][0],     Sc[2 * g][1]);
            PH[g][1] = h2(Sc[2 * g][2],     Sc[2 * g][3]);
            PH[g][2] = h2(Sc[2 * g + 1][0], Sc[2 * g + 1][1]);
            PH[g][3] = h2(Sc[2 * g + 1][2], Sc[2 * g + 1][3]);
        }

        // ---- store K(ch+1) to other buffer; reuse regs to prefetch V(ch+1) ----
        if (more) {
            const int j1 = j0 + CK;
            char* kd = sm + (b ? OFF_K0 : OFF_K1);
#pragma unroll
            for (int t = 0; t < 4; ++t) {
                int idx = tid + t * 256, row = idx >> 4, c4 = idx & 15;
                *(uint2*)(kd + row * RSB + c4 * 8) =
                    make_uint2(h2(kreg[t].x, kreg[t].y), h2(kreg[t].z, kreg[t].w));
                kreg[t] = *(const float4*)(v + base + (size_t)(j1 + row) * D + c4 * 4);
            }
        }

        // ---- PV + ones-MMA row sums on buffer b ----
#pragma unroll
        for (int k2 = 0; k2 < 4; ++k2) {
            if (!act[k2]) continue;
            mma_f16(Lone, PH[k2], ones2);
#pragma unroll
            for (int dg = 0; dg < 4; ++dg) {
                u32 v4[4];
                ldsm_x4t(v4, vb_s + vq_b + (u32)(k2 * 16 * RSB + dg * 32));
                mma_f16(O[2 * dg], PH[k2], v4);
                mma_f16(O[2 * dg + 1], PH[k2], v4 + 2);
            }
        }

        // ---- store V(ch+1) to other buffer ----
        if (more) {
            char* vd = sm + (b ? OFF_V0 : OFF_V1);
#pragma unroll
            for (int t = 0; t < 4; ++t) {
                int idx = tid + t * 256, row = idx >> 4, c4 = idx & 15;
                *(uint2*)(vd + row * RSB + c4 * 8) =
                    make_uint2(h2(kreg[t].x, kreg[t].y), h2(kreg[t].z, kreg[t].w));
            }
        }
        __syncthreads();
    }

    // ---- finalize: Lone fragment holds full row sums (no shfl needed) ----
#pragma unroll
    for (int up = 0; up < 2; ++up) {
        float inv = 1.f / Lone[2 * up];
        int i = ilo + (lane >> 2) + up * 8;
#pragma unroll
        for (int nt = 0; nt < 8; ++nt) {
            int dcol = nt * 8 + (lane & 3) * 2;
            *(float2*)(out + base + (size_t)i * D + dcol) =
                make_float2(O[nt][2 * up] * inv, O[nt][2 * up + 1] * inv);
        }
    }
}

// =====================================================================
// global-prefix path: one 128-thread half handles one split (4 chunks).
// =====================================================================
__device__ __forceinline__ void global_body(
    char* sm, u32 sb, const float* __restrict__ q, const float* __restrict__ k,
    const float* __restrict__ v, int bh, int sp, int htid) {
    const int w = htid >> 5, lane = htid & 31;
    const size_t base = (size_t)bh * S * D;
    const int k0 = sp * KPS;
    const u32 ones2[2] = {0x3C003C00u, 0x3C003C00u};

    {
        const int row = htid >> 1, hf = htid & 1;
        const float4* qp = (const float4*)(q + base + (size_t)row * D + hf * 32);
        const float sc = SCALE * LOG2E;
#pragma unroll
        for (int t = 0; t < 8; ++t) {
            float4 x = qp[t];
            *(uint2*)(sm + GOFF_Q + (u32)(row * RSB + hf * 64 + t * 8)) =
                make_uint2(h2(x.x * sc, x.y * sc), h2(x.z * sc, x.w * sc));
        }
    }
    __syncthreads();

    const u32 qrow_a = (u32)((w * 16 + (lane & 15)) * RSB + (lane >> 4) * 16);
    u32 aq[16];
#pragma unroll
    for (int ks = 0; ks < 4; ++ks)
        ldsm_x4(aq + 4 * ks, sb + GOFF_Q + qrow_a + (u32)(ks * 32));

    float O[8][4];
#pragma unroll
    for (int nt = 0; nt < 8; ++nt)
#pragma unroll
        for (int c = 0; c < 4; ++c) O[nt][c] = 0.f;
    float Lone[4] = {0.f, 0.f, 0.f, 0.f};

    const u32 kq_b = (u32)(((lane >> 4) * 8 + (lane & 7)) * RSB + ((lane >> 3) & 1) * 16);
    const u32 vq_b = (u32)((lane & 15) * RSB + (lane >> 4) * 16);

#pragma unroll 1
    for (int ch = 0; ch < KPS / CK; ++ch) {
        const int j0 = k0 + ch * CK;

        __syncthreads();
        {
            const int r = htid >> 1, hf = htid & 1;
            const float4* kp = (const float4*)(k + base + (size_t)(j0 + r) * D + hf * 32);
            const float4* vp = (const float4*)(v + base + (size_t)(j0 + r) * D + hf * 32);
#pragma unroll
            for (int t = 0; t < 8; ++t) {
                u32 o = (u32)(r * RSB + hf * 64 + t * 8);
                float4 x = kp[t];
                *(uint2*)(sm + GOFF_K + o) = make_uint2(h2(x.x, x.y), h2(x.z, x.w));
                float4 y = vp[t];
                *(uint2*)(sm + GOFF_V + o) = make_uint2(h2(y.x, y.y), h2(y.z, y.w));
            }
        }
        __syncthreads();

        float Sc[8][4];
#pragma unroll
        for (int nt = 0; nt < 8; ++nt)
#pragma unroll
            for (int c = 0; c < 4; ++c) Sc[nt][c] = 0.f;

#pragma unroll
        for (int ntp = 0; ntp < 4; ++ntp) {
#pragma unroll
            for (int ks = 0; ks < 4; ++ks) {
                u32 b4[4];
                ldsm_x4(b4, sb + GOFF_K + kq_b + (u32)(ntp * 16 * RSB + ks * 32));
                mma_f16(Sc[2 * ntp], aq + 4 * ks, b4);
                mma_f16(Sc[2 * ntp + 1], aq + 4 * ks, b4 + 2);
            }
        }

        u32 PH[4][4];
#pragma unroll
        for (int nt = 0; nt < 8; ++nt)
#pragma unroll
            for (int c = 0; c < 4; ++c) Sc[nt][c] = ex2f(Sc[nt][c]);
#pragma unroll
        for (int k2 = 0; k2 < 4; ++k2) {
            PH[k2][0] = h2(Sc[2 * k2][0],     Sc[2 * k2][1]);
            PH[k2][1] = h2(Sc[2 * k2][2],     Sc[2 * k2][3]);
            PH[k2][2] = h2(Sc[2 * k2 + 1][0], Sc[2 * k2 + 1][1]);
            PH[k2][3] = h2(Sc[2 * k2 + 1][2], Sc[2 * k2 + 1][3]);
        }

#pragma unroll
        for (int k2 = 0; k2 < 4; ++k2) {
            mma_f16(Lone, PH[k2], ones2);
#pragma unroll
            for (int dg = 0; dg < 4; ++dg) {
                u32 v4[4];
                ldsm_x4t(v4, sb + GOFF_V + vq_b + (u32)(k2 * 16 * RSB + dg * 32));
                mma_f16(O[2 * dg], PH[k2], v4);
                mma_f16(O[2 * dg + 1], PH[k2], v4 + 2);
            }
        }
    }

#pragma unroll
    for (int up = 0; up < 2; ++up) {
        int i = w * 16 + (lane >> 2) + up * 8;
        if ((lane & 3) == 0) g_pl[bh][sp][i] = Lone[2 * up];
#pragma unroll
        for (int nt = 0; nt < 8; ++nt) {
            int dcol = nt * 8 + (lane & 3) * 2;
            *(float2*)&g_pacc[bh][sp][i][dcol] =
                make_float2(O[nt][2 * up], O[nt][2 * up + 1]);
        }
    }
}

// =====================================================================
// Merged kernel: x<32 -> banded tile; x>=32 -> two global split-halves.
// =====================================================================
__global__ void __launch_bounds__(256, 2)
swa_fused(const float* __restrict__ q, const float* __restrict__ k,
          const float* __restrict__ v, float* __restrict__ out) {
    extern __shared__ __align__(128) char sm[];
    const u32 sb0 = smem_u32(sm);
    const int bh = blockIdx.y;

    if (blockIdx.x < (S / QB)) {
        banded_body(sm, sb0, q, k, v, out, bh, blockIdx.x * QB);
    } else {
        const int half = threadIdx.x >> 7;          // 0/1
        const int htid = threadIdx.x & 127;
        const int sp = (blockIdx.x - (S / QB)) * 2 + half;
        global_body(sm + half * GHB, sb0 + half * GHB, q, k, v, bh, sp, htid);
    }
}

// =====================================================================
// combine split-K partials (plain sums), overwrite rows [0, GQ)
// =====================================================================
__global__ void __launch_bounds__(D, 1)
swa_combine(float* __restrict__ out) {
    const int bh = blockIdx.y;
    const int qi = blockIdx.x;
    const int d = threadIdx.x;

    float den = 0.f, num = 0.f;
#pragma unroll
    for (int s = 0; s < SPLITS; ++s) {
        den += g_pl[bh][s][qi];
        num += g_pacc[bh][s][qi][d];
    }
    out[(size_t)bh * S * D + (size_t)qi * D + d] = num / den;
}

// =====================================================================
extern "C" void kernel_launch(void* const* d_in, const int* in_sizes, int n_in,
                              void* d_out, int out_size) {
    const float* q = (const float*)d_in[0];
    const float* k = (const float*)d_in[1];
    const float* v = (const float*)d_in[2];
    float* out = (float*)d_out;
    (void)in_sizes; (void)n_in; (void)out_size;

    cudaFuncSetAttribute(swa_fused,
                         cudaFuncAttributeMaxDynamicSharedMemorySize, SMEM_BYTES);

    dim3 g1(S / QB + SPLITS / 2, BH);   // 32 banded tiles + 8 global pairs
    swa_fused<<<g1, 256, SMEM_BYTES>>>(q, k, v, out);

    dim3 g3(GQ, BH);
    swa_combine<<<g3, D>>>(out);
}